// round 1
// baseline (speedup 1.0000x reference)
#include <cuda_runtime.h>
#include <cuda_bf16.h>
#include <cstdint>

// ---------------- scratch (device globals: the sanctioned no-alloc path) ---
// b=4, c=512, l=4096
__device__ float g_h[4ull * 512 * 4096];   // groupnorm output
__device__ float g_q[4ull * 512 * 4096];
__device__ float g_k[4ull * 512 * 4096];
__device__ float g_v[4ull * 512 * 4096];
__device__ float g_s[4ull * 4096 * 4096];  // attention scores (256 MB)
__device__ float g_o[4ull * 512 * 4096];   // attention output

#define BM 128
#define BN 128
#define BK 16

// ---------------- GroupNorm: 32 groups, group = 16 ch x 4096 = 65536 elems -
__global__ void __launch_bounds__(256) groupnorm_kernel(
    const float* __restrict__ x, const float* __restrict__ scale,
    const float* __restrict__ bias, float* __restrict__ h)
{
    const int GV = 16384;  // float4 per group
    size_t base4 = (size_t)blockIdx.x * GV;
    const float4* xp = (const float4*)x + base4;

    float s = 0.f, ss = 0.f;
    for (int i = threadIdx.x; i < GV; i += 256) {
        float4 t = xp[i];
        s  += t.x + t.y + t.z + t.w;
        ss += t.x * t.x + t.y * t.y + t.z * t.z + t.w * t.w;
    }
    __shared__ float shs[8], shss[8];
    __shared__ float s_mean, s_rstd;
    int lane = threadIdx.x & 31, wrp = threadIdx.x >> 5;
#pragma unroll
    for (int o = 16; o; o >>= 1) {
        s  += __shfl_xor_sync(0xffffffffu, s, o);
        ss += __shfl_xor_sync(0xffffffffu, ss, o);
    }
    if (lane == 0) { shs[wrp] = s; shss[wrp] = ss; }
    __syncthreads();
    if (threadIdx.x == 0) {
        float ts = 0.f, tss = 0.f;
        for (int i = 0; i < 8; i++) { ts += shs[i]; tss += shss[i]; }
        float mean = ts / 65536.0f;
        float var  = tss / 65536.0f - mean * mean;
        s_mean = mean;
        s_rstd = rsqrtf(var + 1e-6f);
    }
    __syncthreads();
    float mean = s_mean, rstd = s_rstd;

    int g = blockIdx.x & 31;
    float4* hp = (float4*)h + base4;
    for (int i = threadIdx.x; i < GV; i += 256) {
        int ch = g * 16 + (i >> 10);           // 1024 float4 per channel
        float sc = scale[ch] * rstd;
        float bi = bias[ch] - mean * sc;
        float4 t = xp[i];
        t.x = t.x * sc + bi; t.y = t.y * sc + bi;
        t.z = t.z * sc + bi; t.w = t.w * sc + bi;
        hp[i] = t;
    }
}

// ---------------- GEMM NN: C[b][m][n] = sum_k A[m][k] * B[b][k][n] + bias[m]
// M=512, N=4096, K=512. A=weights (not batched). Optional residual.
__global__ void __launch_bounds__(256) gemm_nn_kernel(
    const float* __restrict__ A, const float* __restrict__ B,
    const float* __restrict__ bias, const float* __restrict__ resid,
    float* __restrict__ C)
{
    const int K = 512;
    __shared__ float As[BK][BM + 4];
    __shared__ float Bs[BK][BN];
    int tid = threadIdx.x;
    int tx = tid & 15, ty = tid >> 4;
    int m0 = blockIdx.y * BM;
    int n0 = blockIdx.x * BN;
    const float* Bp = B + (size_t)blockIdx.z * 2097152 + n0;

    float acc[8][8] = {};
    for (int k0 = 0; k0 < K; k0 += BK) {
        {
            int kk = tid & 15;
            for (int m = tid >> 4; m < BM; m += 16)
                As[kk][m] = A[(m0 + m) * K + k0 + kk];
        }
        {
            int n = tid & 127;
            for (int kk = tid >> 7; kk < BK; kk += 2)
                Bs[kk][n] = Bp[(size_t)(k0 + kk) * 4096 + n];
        }
        __syncthreads();
#pragma unroll
        for (int kk = 0; kk < BK; kk++) {
            float4 a0 = *(const float4*)&As[kk][ty * 8];
            float4 a1 = *(const float4*)&As[kk][ty * 8 + 4];
            float4 b0 = *(const float4*)&Bs[kk][tx * 8];
            float4 b1 = *(const float4*)&Bs[kk][tx * 8 + 4];
            float ar[8] = {a0.x, a0.y, a0.z, a0.w, a1.x, a1.y, a1.z, a1.w};
            float br[8] = {b0.x, b0.y, b0.z, b0.w, b1.x, b1.y, b1.z, b1.w};
#pragma unroll
            for (int r = 0; r < 8; r++)
#pragma unroll
                for (int c = 0; c < 8; c++) acc[r][c] += ar[r] * br[c];
        }
        __syncthreads();
    }

    float* Cp = C + (size_t)blockIdx.z * 2097152;
    const float* Rp = resid ? resid + (size_t)blockIdx.z * 2097152 : nullptr;
#pragma unroll
    for (int r = 0; r < 8; r++) {
        int m = m0 + ty * 8 + r;
        float bv = bias[m];
#pragma unroll
        for (int c = 0; c < 8; c++) {
            int n = n0 + tx * 8 + c;
            size_t idx = (size_t)m * 4096 + n;
            float val = acc[r][c] + bv;
            if (Rp) val += Rp[idx];
            Cp[idx] = val;
        }
    }
}

// ---------------- GEMM TN (scores): S[b][i][j] = scale * sum_c Q[b][c][i] K[b][c][j]
// M=N=4096, K=512
__global__ void __launch_bounds__(256) gemm_tn_kernel(
    const float* __restrict__ Q, const float* __restrict__ Kt,
    float* __restrict__ S)
{
    const int K = 512;
    const float SCALE = 0.044194173824159216f;  // 512^-0.5
    __shared__ float As[BK][BM];
    __shared__ float Bs[BK][BN];
    int tid = threadIdx.x;
    int tx = tid & 15, ty = tid >> 4;
    int m0 = blockIdx.y * BM;
    int n0 = blockIdx.x * BN;
    const float* Qp = Q + (size_t)blockIdx.z * 2097152;
    const float* Kp = Kt + (size_t)blockIdx.z * 2097152;

    float acc[8][8] = {};
    for (int k0 = 0; k0 < K; k0 += BK) {
        {
            int mn = tid & 127;
            for (int kk = tid >> 7; kk < BK; kk += 2) {
                As[kk][mn] = Qp[(size_t)(k0 + kk) * 4096 + m0 + mn];
                Bs[kk][mn] = Kp[(size_t)(k0 + kk) * 4096 + n0 + mn];
            }
        }
        __syncthreads();
#pragma unroll
        for (int kk = 0; kk < BK; kk++) {
            float4 a0 = *(const float4*)&As[kk][ty * 8];
            float4 a1 = *(const float4*)&As[kk][ty * 8 + 4];
            float4 b0 = *(const float4*)&Bs[kk][tx * 8];
            float4 b1 = *(const float4*)&Bs[kk][tx * 8 + 4];
            float ar[8] = {a0.x, a0.y, a0.z, a0.w, a1.x, a1.y, a1.z, a1.w};
            float br[8] = {b0.x, b0.y, b0.z, b0.w, b1.x, b1.y, b1.z, b1.w};
#pragma unroll
            for (int r = 0; r < 8; r++)
#pragma unroll
                for (int c = 0; c < 8; c++) acc[r][c] += ar[r] * br[c];
        }
        __syncthreads();
    }

    float* Sp = S + (size_t)blockIdx.z * 16777216;
#pragma unroll
    for (int r = 0; r < 8; r++) {
        int m = m0 + ty * 8 + r;
#pragma unroll
        for (int c = 0; c < 8; c++) {
            int n = n0 + tx * 8 + c;
            Sp[(size_t)m * 4096 + n] = acc[r][c] * SCALE;
        }
    }
}

// ---------------- row softmax over j: 16384 rows of 4096 ------------------
__global__ void __launch_bounds__(256) softmax_kernel(float* __restrict__ S)
{
    __shared__ float shm[8], shsum[8];
    __shared__ float bmax, bsum;
    float* p = S + (size_t)blockIdx.x * 4096;
    float v[16];
    float mx = -3.4e38f;
#pragma unroll
    for (int i = 0; i < 16; i++) {
        v[i] = p[threadIdx.x + (i << 8)];
        mx = fmaxf(mx, v[i]);
    }
    int lane = threadIdx.x & 31, wrp = threadIdx.x >> 5;
#pragma unroll
    for (int o = 16; o; o >>= 1) mx = fmaxf(mx, __shfl_xor_sync(0xffffffffu, mx, o));
    if (lane == 0) shm[wrp] = mx;
    __syncthreads();
    if (threadIdx.x == 0) {
        float m = shm[0];
        for (int i = 1; i < 8; i++) m = fmaxf(m, shm[i]);
        bmax = m;
    }
    __syncthreads();
    mx = bmax;
    float sum = 0.f;
#pragma unroll
    for (int i = 0; i < 16; i++) { v[i] = __expf(v[i] - mx); sum += v[i]; }
#pragma unroll
    for (int o = 16; o; o >>= 1) sum += __shfl_xor_sync(0xffffffffu, sum, o);
    if (lane == 0) shsum[wrp] = sum;
    __syncthreads();
    if (threadIdx.x == 0) {
        float s = 0.f;
        for (int i = 0; i < 8; i++) s += shsum[i];
        bsum = s;
    }
    __syncthreads();
    float inv = 1.0f / bsum;
#pragma unroll
    for (int i = 0; i < 16; i++) p[threadIdx.x + (i << 8)] = v[i] * inv;
}

// ---------------- GEMM NT (attn out): O[b][c][i] = sum_j V[b][c][j] W[b][i][j]
// M=512 (c), N=4096 (i), K=4096 (j)
__global__ void __launch_bounds__(256) gemm_nt_kernel(
    const float* __restrict__ V, const float* __restrict__ S,
    float* __restrict__ O)
{
    const int K = 4096;
    __shared__ float As[BK][BM + 4];
    __shared__ float Bs[BK][BN + 4];
    int tid = threadIdx.x;
    int tx = tid & 15, ty = tid >> 4;
    int m0 = blockIdx.y * BM;
    int n0 = blockIdx.x * BN;
    const float* Vp = V + (size_t)blockIdx.z * 2097152;
    const float* Sp = S + (size_t)blockIdx.z * 16777216;

    float acc[8][8] = {};
    for (int k0 = 0; k0 < K; k0 += BK) {
        {
            int kk = tid & 15;
            for (int m = tid >> 4; m < BM; m += 16) {
                As[kk][m] = Vp[(size_t)(m0 + m) * 4096 + k0 + kk];
                Bs[kk][m] = Sp[(size_t)(n0 + m) * 4096 + k0 + kk];
            }
        }
        __syncthreads();
#pragma unroll
        for (int kk = 0; kk < BK; kk++) {
            float4 a0 = *(const float4*)&As[kk][ty * 8];
            float4 a1 = *(const float4*)&As[kk][ty * 8 + 4];
            float4 b0 = *(const float4*)&Bs[kk][tx * 8];
            float4 b1 = *(const float4*)&Bs[kk][tx * 8 + 4];
            float ar[8] = {a0.x, a0.y, a0.z, a0.w, a1.x, a1.y, a1.z, a1.w};
            float br[8] = {b0.x, b0.y, b0.z, b0.w, b1.x, b1.y, b1.z, b1.w};
#pragma unroll
            for (int r = 0; r < 8; r++)
#pragma unroll
                for (int c = 0; c < 8; c++) acc[r][c] += ar[r] * br[c];
        }
        __syncthreads();
    }

    float* Op = O + (size_t)blockIdx.z * 2097152;
#pragma unroll
    for (int r = 0; r < 8; r++) {
        int m = m0 + ty * 8 + r;
#pragma unroll
        for (int c = 0; c < 8; c++) {
            int n = n0 + tx * 8 + c;
            Op[(size_t)m * 4096 + n] = acc[r][c];
        }
    }
}

// ---------------------------------------------------------------------------
extern "C" void kernel_launch(void* const* d_in, const int* in_sizes, int n_in,
                              void* d_out, int out_size)
{
    (void)in_sizes; (void)n_in; (void)out_size;
    const float* x  = (const float*)d_in[0];
    const float* gs = (const float*)d_in[1];
    const float* gb = (const float*)d_in[2];
    const float* wq = (const float*)d_in[3];
    const float* bq = (const float*)d_in[4];
    const float* wk = (const float*)d_in[5];
    const float* bk = (const float*)d_in[6];
    const float* wv = (const float*)d_in[7];
    const float* bv = (const float*)d_in[8];
    const float* wp = (const float*)d_in[9];
    const float* bp = (const float*)d_in[10];
    float* out = (float*)d_out;

    float *h, *q, *k, *v, *s, *o;
    cudaGetSymbolAddress((void**)&h, g_h);
    cudaGetSymbolAddress((void**)&q, g_q);
    cudaGetSymbolAddress((void**)&k, g_k);
    cudaGetSymbolAddress((void**)&v, g_v);
    cudaGetSymbolAddress((void**)&s, g_s);
    cudaGetSymbolAddress((void**)&o, g_o);

    groupnorm_kernel<<<128, 256>>>(x, gs, gb, h);

    dim3 gproj(32, 4, 4);   // N/128, M/128, batch
    gemm_nn_kernel<<<gproj, 256>>>(wq, h, bq, nullptr, q);
    gemm_nn_kernel<<<gproj, 256>>>(wk, h, bk, nullptr, k);
    gemm_nn_kernel<<<gproj, 256>>>(wv, h, bv, nullptr, v);

    gemm_tn_kernel<<<dim3(32, 32, 4), 256>>>(q, k, s);
    softmax_kernel<<<16384, 256>>>(s);
    gemm_nt_kernel<<<gproj, 256>>>(v, s, o);

    gemm_nn_kernel<<<gproj, 256>>>(wp, o, bp, x, out);
}

// round 2
// speedup vs baseline: 2.6476x; 2.6476x over previous
#include <cuda_runtime.h>
#include <cuda_bf16.h>
#include <cstdint>

// scratch (device globals) — b=4, c=512, l=4096
__device__ float g_h[4ull * 512 * 4096];
__device__ float g_q[4ull * 512 * 4096];
__device__ float g_k[4ull * 512 * 4096];
__device__ float g_v[4ull * 512 * 4096];
__device__ float g_s[4ull * 4096 * 4096];
__device__ float g_o[4ull * 512 * 4096];

#define BM 128
#define BN 128
#define BK 16

// ---------------- tf32 helpers ---------------------------------------------
__device__ __forceinline__ uint32_t f2t(float x) {
    uint32_t r;
    asm("cvt.rna.tf32.f32 %0, %1;" : "=r"(r) : "f"(x));
    return r;
}

__device__ __forceinline__ void mma8(float (&c)[4], const uint32_t (&a)[4],
                                     const uint32_t (&b)[2]) {
    asm volatile(
        "mma.sync.aligned.m16n8k8.row.col.f32.tf32.tf32.f32 "
        "{%0,%1,%2,%3},{%4,%5,%6,%7},{%8,%9},{%0,%1,%2,%3};"
        : "+f"(c[0]), "+f"(c[1]), "+f"(c[2]), "+f"(c[3])
        : "r"(a[0]), "r"(a[1]), "r"(a[2]), "r"(a[3]), "r"(b[0]), "r"(b[1]));
}

// stage 16(k) x 128(n) tile, src row-major in k (src[k*ld + n]) -> D[k][n]
__device__ __forceinline__ void stage_direct(uint32_t (*D)[BN + 8],
                                             const float* __restrict__ src,
                                             int ld, int tid) {
#pragma unroll
    for (int r = 0; r < 2; r++) {
        int idx = tid + r * 256;
        int k = idx >> 5;
        int n4 = (idx & 31) << 2;
        float4 t = *(const float4*)(src + (size_t)k * ld + n4);
        D[k][n4 + 0] = f2t(t.x);
        D[k][n4 + 1] = f2t(t.y);
        D[k][n4 + 2] = f2t(t.z);
        D[k][n4 + 3] = f2t(t.w);
    }
}

// stage 128(m) x 16(k) tile, src row-major in m (src[m*ld + k]) -> D[k][m]
__device__ __forceinline__ void stage_trans(uint32_t (*D)[BM + 8],
                                            const float* __restrict__ src,
                                            int ld, int tid) {
#pragma unroll
    for (int r = 0; r < 2; r++) {
        int idx = tid + r * 256;
        int m = idx >> 2;
        int k4 = (idx & 3) << 2;
        float4 t = *(const float4*)(src + (size_t)m * ld + k4);
        D[k4 + 0][m] = f2t(t.x);
        D[k4 + 1][m] = f2t(t.y);
        D[k4 + 2][m] = f2t(t.z);
        D[k4 + 3][m] = f2t(t.w);
    }
}

// compute one BK slice: 8 warps, warp = 64(m) x 32(n), two k-steps of 8
__device__ __forceinline__ void mma_slice(const uint32_t (*As)[BM + 8],
                                          const uint32_t (*Bs)[BN + 8],
                                          float (&acc)[4][4][4], int lane,
                                          int wm, int wn) {
#pragma unroll
    for (int ks = 0; ks < 2; ks++) {
        int kk = ks * 8 + (lane & 3);
        uint32_t a[4][4], b[4][2];
#pragma unroll
        for (int i = 0; i < 4; i++) {
            int m = wm * 64 + i * 16 + (lane >> 2);
            a[i][0] = As[kk][m];
            a[i][1] = As[kk][m + 8];
            a[i][2] = As[kk + 4][m];
            a[i][3] = As[kk + 4][m + 8];
        }
#pragma unroll
        for (int j = 0; j < 4; j++) {
            int n = wn * 32 + j * 8 + (lane >> 2);
            b[j][0] = Bs[kk][n];
            b[j][1] = Bs[kk + 4][n];
        }
#pragma unroll
        for (int i = 0; i < 4; i++)
#pragma unroll
            for (int j = 0; j < 4; j++) mma8(acc[i][j], a[i], b[j]);
    }
}

// ---------------- GroupNorm --------------------------------------------------
__global__ void __launch_bounds__(256) groupnorm_kernel(
    const float* __restrict__ x, const float* __restrict__ scale,
    const float* __restrict__ bias, float* __restrict__ h)
{
    const int GV = 16384;
    size_t base4 = (size_t)blockIdx.x * GV;
    const float4* xp = (const float4*)x + base4;

    float s = 0.f, ss = 0.f;
    for (int i = threadIdx.x; i < GV; i += 256) {
        float4 t = xp[i];
        s  += t.x + t.y + t.z + t.w;
        ss += t.x * t.x + t.y * t.y + t.z * t.z + t.w * t.w;
    }
    __shared__ float shs[8], shss[8];
    __shared__ float s_mean, s_rstd;
    int lane = threadIdx.x & 31, wrp = threadIdx.x >> 5;
#pragma unroll
    for (int o = 16; o; o >>= 1) {
        s  += __shfl_xor_sync(0xffffffffu, s, o);
        ss += __shfl_xor_sync(0xffffffffu, ss, o);
    }
    if (lane == 0) { shs[wrp] = s; shss[wrp] = ss; }
    __syncthreads();
    if (threadIdx.x == 0) {
        float ts = 0.f, tss = 0.f;
        for (int i = 0; i < 8; i++) { ts += shs[i]; tss += shss[i]; }
        float mean = ts / 65536.0f;
        float var  = tss / 65536.0f - mean * mean;
        s_mean = mean;
        s_rstd = rsqrtf(var + 1e-6f);
    }
    __syncthreads();
    float mean = s_mean, rstd = s_rstd;

    int g = blockIdx.x & 31;
    float4* hp = (float4*)h + base4;
    for (int i = threadIdx.x; i < GV; i += 256) {
        int ch = g * 16 + (i >> 10);
        float sc = scale[ch] * rstd;
        float bi = bias[ch] - mean * sc;
        float4 t = xp[i];
        t.x = t.x * sc + bi; t.y = t.y * sc + bi;
        t.z = t.z * sc + bi; t.w = t.w * sc + bi;
        hp[i] = t;
    }
}

// ---------------- NN proj: C[b][m][n] = sum_k W[m][k] H[b][k][n] + bias[m] (+resid)
__global__ void __launch_bounds__(256, 2) gemm_nn_kernel(
    const float* __restrict__ W, const float* __restrict__ H,
    const float* __restrict__ bias, const float* __restrict__ resid,
    float* __restrict__ C)
{
    __shared__ uint32_t As[BK][BM + 8];
    __shared__ uint32_t Bs[BK][BN + 8];
    int tid = threadIdx.x, lane = tid & 31, wid = tid >> 5;
    int wm = wid & 1, wn = wid >> 1;
    int m0 = blockIdx.y * BM, n0 = blockIdx.x * BN;
    const float* Hp = H + (size_t)blockIdx.z * 2097152;

    float acc[4][4][4] = {};
    for (int k0 = 0; k0 < 512; k0 += BK) {
        stage_trans(As, W + (size_t)m0 * 512 + k0, 512, tid);
        stage_direct(Bs, Hp + (size_t)k0 * 4096 + n0, 4096, tid);
        __syncthreads();
        mma_slice(As, Bs, acc, lane, wm, wn);
        __syncthreads();
    }

    float* Cp = C + (size_t)blockIdx.z * 2097152;
    const float* Rp = resid ? resid + (size_t)blockIdx.z * 2097152 : nullptr;
#pragma unroll
    for (int i = 0; i < 4; i++) {
        int r0 = m0 + wm * 64 + i * 16 + (lane >> 2);
        float bv0 = bias[r0], bv1 = bias[r0 + 8];
#pragma unroll
        for (int j = 0; j < 4; j++) {
            int cc = n0 + wn * 32 + j * 8 + 2 * (lane & 3);
            size_t i0 = (size_t)r0 * 4096 + cc;
            size_t i1 = (size_t)(r0 + 8) * 4096 + cc;
            float2 v0 = {acc[i][j][0] + bv0, acc[i][j][1] + bv0};
            float2 v1 = {acc[i][j][2] + bv1, acc[i][j][3] + bv1};
            if (Rp) {
                float2 q0 = *(const float2*)(Rp + i0);
                float2 q1 = *(const float2*)(Rp + i1);
                v0.x += q0.x; v0.y += q0.y; v1.x += q1.x; v1.y += q1.y;
            }
            *(float2*)(Cp + i0) = v0;
            *(float2*)(Cp + i1) = v1;
        }
    }
}

// ---------------- TN scores: S[b][i][j] = scale * sum_c Q[b][c][i] K[b][c][j]
__global__ void __launch_bounds__(256, 2) gemm_tn_kernel(
    const float* __restrict__ Q, const float* __restrict__ Kt,
    float* __restrict__ S)
{
    const float SCALE = 0.044194173824159216f;
    __shared__ uint32_t As[BK][BM + 8];
    __shared__ uint32_t Bs[BK][BN + 8];
    int tid = threadIdx.x, lane = tid & 31, wid = tid >> 5;
    int wm = wid & 1, wn = wid >> 1;
    int m0 = blockIdx.y * BM, n0 = blockIdx.x * BN;
    const float* Qp = Q + (size_t)blockIdx.z * 2097152;
    const float* Kp = Kt + (size_t)blockIdx.z * 2097152;

    float acc[4][4][4] = {};
    for (int k0 = 0; k0 < 512; k0 += BK) {
        stage_direct(As, Qp + (size_t)k0 * 4096 + m0, 4096, tid);
        stage_direct(Bs, Kp + (size_t)k0 * 4096 + n0, 4096, tid);
        __syncthreads();
        mma_slice(As, Bs, acc, lane, wm, wn);
        __syncthreads();
    }

    float* Sp = S + (size_t)blockIdx.z * 16777216;
#pragma unroll
    for (int i = 0; i < 4; i++) {
        int r0 = m0 + wm * 64 + i * 16 + (lane >> 2);
#pragma unroll
        for (int j = 0; j < 4; j++) {
            int cc = n0 + wn * 32 + j * 8 + 2 * (lane & 3);
            float2 v0 = {acc[i][j][0] * SCALE, acc[i][j][1] * SCALE};
            float2 v1 = {acc[i][j][2] * SCALE, acc[i][j][3] * SCALE};
            *(float2*)(Sp + (size_t)r0 * 4096 + cc) = v0;
            *(float2*)(Sp + (size_t)(r0 + 8) * 4096 + cc) = v1;
        }
    }
}

// ---------------- NT attn out: O[b][c][i] = sum_j V[b][c][j] S[b][i][j]
__global__ void __launch_bounds__(256, 2) gemm_nt_kernel(
    const float* __restrict__ V, const float* __restrict__ S,
    float* __restrict__ O)
{
    __shared__ uint32_t As[BK][BM + 8];
    __shared__ uint32_t Bs[BK][BN + 8];
    int tid = threadIdx.x, lane = tid & 31, wid = tid >> 5;
    int wm = wid & 1, wn = wid >> 1;
    int m0 = blockIdx.y * BM, n0 = blockIdx.x * BN;
    const float* Vp = V + (size_t)blockIdx.z * 2097152;
    const float* Sp = S + (size_t)blockIdx.z * 16777216;

    float acc[4][4][4] = {};
    for (int k0 = 0; k0 < 4096; k0 += BK) {
        stage_trans(As, Vp + (size_t)m0 * 4096 + k0, 4096, tid);
        stage_trans(Bs, Sp + (size_t)n0 * 4096 + k0, 4096, tid);
        __syncthreads();
        mma_slice(As, Bs, acc, lane, wm, wn);
        __syncthreads();
    }

    float* Op = O + (size_t)blockIdx.z * 2097152;
#pragma unroll
    for (int i = 0; i < 4; i++) {
        int r0 = m0 + wm * 64 + i * 16 + (lane >> 2);
#pragma unroll
        for (int j = 0; j < 4; j++) {
            int cc = n0 + wn * 32 + j * 8 + 2 * (lane & 3);
            *(float2*)(Op + (size_t)r0 * 4096 + cc) =
                make_float2(acc[i][j][0], acc[i][j][1]);
            *(float2*)(Op + (size_t)(r0 + 8) * 4096 + cc) =
                make_float2(acc[i][j][2], acc[i][j][3]);
        }
    }
}

// ---------------- row softmax over j -----------------------------------------
__global__ void __launch_bounds__(256) softmax_kernel(float* __restrict__ S)
{
    __shared__ float shm[8], shsum[8];
    __shared__ float bmax, bsum;
    float* p = S + (size_t)blockIdx.x * 4096;
    float v[16];
    float mx = -3.4e38f;
#pragma unroll
    for (int i = 0; i < 16; i++) {
        v[i] = p[threadIdx.x + (i << 8)];
        mx = fmaxf(mx, v[i]);
    }
    int lane = threadIdx.x & 31, wrp = threadIdx.x >> 5;
#pragma unroll
    for (int o = 16; o; o >>= 1) mx = fmaxf(mx, __shfl_xor_sync(0xffffffffu, mx, o));
    if (lane == 0) shm[wrp] = mx;
    __syncthreads();
    if (threadIdx.x == 0) {
        float m = shm[0];
        for (int i = 1; i < 8; i++) m = fmaxf(m, shm[i]);
        bmax = m;
    }
    __syncthreads();
    mx = bmax;
    float sum = 0.f;
#pragma unroll
    for (int i = 0; i < 16; i++) { v[i] = __expf(v[i] - mx); sum += v[i]; }
#pragma unroll
    for (int o = 16; o; o >>= 1) sum += __shfl_xor_sync(0xffffffffu, sum, o);
    if (lane == 0) shsum[wrp] = sum;
    __syncthreads();
    if (threadIdx.x == 0) {
        float s = 0.f;
        for (int i = 0; i < 8; i++) s += shsum[i];
        bsum = s;
    }
    __syncthreads();
    float inv = 1.0f / bsum;
#pragma unroll
    for (int i = 0; i < 16; i++) p[threadIdx.x + (i << 8)] = v[i] * inv;
}

// -----------------------------------------------------------------------------
extern "C" void kernel_launch(void* const* d_in, const int* in_sizes, int n_in,
                              void* d_out, int out_size)
{
    (void)in_sizes; (void)n_in; (void)out_size;
    const float* x  = (const float*)d_in[0];
    const float* gs = (const float*)d_in[1];
    const float* gb = (const float*)d_in[2];
    const float* wq = (const float*)d_in[3];
    const float* bq = (const float*)d_in[4];
    const float* wk = (const float*)d_in[5];
    const float* bk = (const float*)d_in[6];
    const float* wv = (const float*)d_in[7];
    const float* bv = (const float*)d_in[8];
    const float* wp = (const float*)d_in[9];
    const float* bp = (const float*)d_in[10];
    float* out = (float*)d_out;

    float *h, *q, *k, *v, *s, *o;
    cudaGetSymbolAddress((void**)&h, g_h);
    cudaGetSymbolAddress((void**)&q, g_q);
    cudaGetSymbolAddress((void**)&k, g_k);
    cudaGetSymbolAddress((void**)&v, g_v);
    cudaGetSymbolAddress((void**)&s, g_s);
    cudaGetSymbolAddress((void**)&o, g_o);

    groupnorm_kernel<<<128, 256>>>(x, gs, gb, h);

    dim3 gproj(32, 4, 4);
    gemm_nn_kernel<<<gproj, 256>>>(wq, h, bq, nullptr, q);
    gemm_nn_kernel<<<gproj, 256>>>(wk, h, bk, nullptr, k);
    gemm_nn_kernel<<<gproj, 256>>>(wv, h, bv, nullptr, v);

    gemm_tn_kernel<<<dim3(32, 32, 4), 256>>>(q, k, s);
    softmax_kernel<<<16384, 256>>>(s);
    gemm_nt_kernel<<<gproj, 256>>>(v, s, o);

    gemm_nn_kernel<<<gproj, 256>>>(wp, o, bp, x, out);
}

// round 4
// speedup vs baseline: 6.3498x; 2.3983x over previous
#include <cuda_runtime.h>
#include <cuda_bf16.h>
#include <cstdint>

// scratch (device globals) — b=4, c=512, l=4096, all intermediates bf16
__device__ __nv_bfloat16 g_ht[4ull * 4096 * 512];   // H^T [b][l][c]
__device__ __nv_bfloat16 g_qt[4ull * 4096 * 512];   // Q^T [b][l][c]
__device__ __nv_bfloat16 g_kt[4ull * 4096 * 512];   // K^T [b][l][c]
__device__ __nv_bfloat16 g_v [4ull * 512 * 4096];   // V   [b][c][l]
__device__ __nv_bfloat16 g_s [4ull * 4096 * 4096];  // S   [b][i][j]
__device__ __nv_bfloat16 g_ot[4ull * 4096 * 512];   // O^T [b][l][c]
__device__ __nv_bfloat16 g_wq[512 * 512], g_wk[512 * 512];
__device__ __nv_bfloat16 g_wv[512 * 512], g_wp[512 * 512];

// ---------------- helpers ----------------------------------------------------
__device__ __forceinline__ uint32_t smem_u32(const void* p) {
    uint32_t a;
    asm("{ .reg .u64 t; cvta.to.shared.u64 t, %1; cvt.u32.u64 %0, t; }"
        : "=r"(a) : "l"(p));
    return a;
}

__device__ __forceinline__ void ldsm4(uint32_t& r0, uint32_t& r1, uint32_t& r2,
                                      uint32_t& r3, uint32_t addr) {
    asm volatile("ldmatrix.sync.aligned.m8n8.x4.shared.b16 {%0,%1,%2,%3}, [%4];"
                 : "=r"(r0), "=r"(r1), "=r"(r2), "=r"(r3) : "r"(addr));
}

__device__ __forceinline__ void mma_bf16(float (&c)[4], const uint32_t (&a)[4],
                                         const uint32_t (&b)[2]) {
    asm volatile(
        "mma.sync.aligned.m16n8k16.row.col.f32.bf16.bf16.f32 "
        "{%0,%1,%2,%3},{%4,%5,%6,%7},{%8,%9},{%0,%1,%2,%3};"
        : "+f"(c[0]), "+f"(c[1]), "+f"(c[2]), "+f"(c[3])
        : "r"(a[0]), "r"(a[1]), "r"(a[2]), "r"(a[3]), "r"(b[0]), "r"(b[1]));
}

// smem: 3 stages x (A 128x(32+8) bf16 = 10240B, B same) = 61440B
#define STG_BYTES 20480
#define ROW_B 80
#define SMEM_TOTAL 61440

// stage one 128x32 bf16 K-major tile pair via cp.async (16B chunks)
__device__ __forceinline__ void load_stage(
    uint32_t sbase, const __nv_bfloat16* __restrict__ Ab,
    const __nv_bfloat16* __restrict__ Bb, int64_t lda, int64_t ldb, int koff,
    int tid) {
#pragma unroll
    for (int rep = 0; rep < 4; rep++) {
        int u = tid + rep * 256;
        int isB = u >> 9;
        int v = u & 511;
        int row = v >> 2, c16 = v & 3;
        const __nv_bfloat16* g =
            (isB ? Bb + (int64_t)row * ldb : Ab + (int64_t)row * lda) + koff +
            c16 * 8;
        uint32_t dst = sbase + isB * 10240 + row * ROW_B + c16 * 16;
        asm volatile("cp.async.cg.shared.global [%0], [%1], 16;"
                     :: "r"(dst), "l"(g) : "memory");
    }
}

// ---------------- generic bf16 tensor-core GEMM -------------------------------
// D[m][n] = alpha * sum_k A[z][m][k] * B[z][n][k]
//           (+bias_m[m]) (+bias_n[n]) (+resid, fp32 out only)
__global__ void __launch_bounds__(256, 2) mm_bf16(
    const __nv_bfloat16* __restrict__ A, int64_t lda, int64_t astr,
    const __nv_bfloat16* __restrict__ B, int64_t ldb, int64_t bstr,
    void* __restrict__ C, int64_t ldc, int64_t cstr, int K, float alpha,
    const float* __restrict__ bias_m, const float* __restrict__ bias_n,
    const float* __restrict__ resid, int out_f32)
{
    extern __shared__ char smem[];
    uint32_t sb = smem_u32(smem);
    int tid = threadIdx.x, lane = tid & 31, wid = tid >> 5;
    int wm = wid & 1, wn = wid >> 1;
    int m0 = blockIdx.y * 128, n0 = blockIdx.x * 128, z = blockIdx.z;
    const __nv_bfloat16* Ab = A + (int64_t)z * astr + (int64_t)m0 * lda;
    const __nv_bfloat16* Bb = B + (int64_t)z * bstr + (int64_t)n0 * ldb;

    const int S = K >> 5;
    // preload stages 0,1
    load_stage(sb, Ab, Bb, lda, ldb, 0, tid);
    asm volatile("cp.async.commit_group;" ::: "memory");
    if (S > 1) load_stage(sb + STG_BYTES, Ab, Bb, lda, ldb, 32, tid);
    asm volatile("cp.async.commit_group;" ::: "memory");

    float acc[4][4][4] = {};
    for (int s = 0; s < S; s++) {
        if (s + 2 < S)
            load_stage(sb + ((s + 2) % 3) * STG_BYTES, Ab, Bb, lda, ldb,
                       (s + 2) * 32, tid);
        asm volatile("cp.async.commit_group;" ::: "memory");
        asm volatile("cp.async.wait_group 2;" ::: "memory");
        __syncthreads();

        uint32_t sa = sb + (s % 3) * STG_BYTES;
        uint32_t sbB = sa + 10240;
#pragma unroll
        for (int kk = 0; kk < 32; kk += 16) {
            uint32_t a[4][4], b[4][2];
#pragma unroll
            for (int i = 0; i < 4; i++) {
                int row = wm * 64 + i * 16 + (lane & 15);
                int col = kk + ((lane >> 4) << 3);
                ldsm4(a[i][0], a[i][1], a[i][2], a[i][3],
                      sa + row * ROW_B + col * 2);
            }
#pragma unroll
            for (int jt = 0; jt < 2; jt++) {
                int row = wn * 32 + jt * 16 + (lane & 7) + ((lane >> 4) << 3);
                int col = kk + (((lane >> 3) & 1) << 3);
                uint32_t r0, r1, r2, r3;
                ldsm4(r0, r1, r2, r3, sbB + row * ROW_B + col * 2);
                b[jt * 2][0] = r0; b[jt * 2][1] = r1;
                b[jt * 2 + 1][0] = r2; b[jt * 2 + 1][1] = r3;
            }
#pragma unroll
            for (int i = 0; i < 4; i++)
#pragma unroll
                for (int j = 0; j < 4; j++) mma_bf16(acc[i][j], a[i], b[j]);
        }
        __syncthreads();
    }

    // epilogue
#pragma unroll
    for (int i = 0; i < 4; i++) {
        int r0 = m0 + wm * 64 + i * 16 + (lane >> 2);
        float bm0 = bias_m ? bias_m[r0] : 0.0f;
        float bm1 = bias_m ? bias_m[r0 + 8] : 0.0f;
#pragma unroll
        for (int j = 0; j < 4; j++) {
            int cc = n0 + wn * 32 + j * 8 + (lane & 3) * 2;
            float v00 = acc[i][j][0] * alpha + bm0;
            float v01 = acc[i][j][1] * alpha + bm0;
            float v10 = acc[i][j][2] * alpha + bm1;
            float v11 = acc[i][j][3] * alpha + bm1;
            if (bias_n) {
                float b0 = bias_n[cc], b1 = bias_n[cc + 1];
                v00 += b0; v01 += b1; v10 += b0; v11 += b1;
            }
            int64_t i0 = (int64_t)z * cstr + (int64_t)r0 * ldc + cc;
            int64_t i1 = i0 + 8 * ldc;
            if (out_f32) {
                float* Cf = (float*)C;
                if (resid) {
                    float2 t0 = *(const float2*)(resid + i0);
                    float2 t1 = *(const float2*)(resid + i1);
                    v00 += t0.x; v01 += t0.y; v10 += t1.x; v11 += t1.y;
                }
                *(float2*)(Cf + i0) = make_float2(v00, v01);
                *(float2*)(Cf + i1) = make_float2(v10, v11);
            } else {
                __nv_bfloat16* Cb = (__nv_bfloat16*)C;
                __nv_bfloat162 h0 = __float22bfloat162_rn(make_float2(v00, v01));
                __nv_bfloat162 h1 = __float22bfloat162_rn(make_float2(v10, v11));
                *(__nv_bfloat162*)(Cb + i0) = h0;
                *(__nv_bfloat162*)(Cb + i1) = h1;
            }
        }
    }
}

// ---------------- weight fp32 -> bf16 -----------------------------------------
__global__ void __launch_bounds__(256) cvt_w_kernel(
    const float* __restrict__ w0, const float* __restrict__ w1,
    const float* __restrict__ w2, const float* __restrict__ w3,
    __nv_bfloat16* __restrict__ o0, __nv_bfloat16* __restrict__ o1,
    __nv_bfloat16* __restrict__ o2, __nv_bfloat16* __restrict__ o3)
{
    const float* w = blockIdx.y == 0 ? w0 : blockIdx.y == 1 ? w1
                     : blockIdx.y == 2 ? w2 : w3;
    __nv_bfloat16* o = blockIdx.y == 0 ? o0 : blockIdx.y == 1 ? o1
                       : blockIdx.y == 2 ? o2 : o3;
    int i = (blockIdx.x * 256 + threadIdx.x) * 4;
    float4 t = *(const float4*)(w + i);
    __nv_bfloat162 p0 = __float22bfloat162_rn(make_float2(t.x, t.y));
    __nv_bfloat162 p1 = __float22bfloat162_rn(make_float2(t.z, t.w));
    *(__nv_bfloat162*)(o + i) = p0;
    *(__nv_bfloat162*)(o + i + 2) = p1;
}

// ---------------- GroupNorm -> transposed bf16 H^T [b][l][c] -------------------
__global__ void __launch_bounds__(256) groupnorm_t_kernel(
    const float* __restrict__ x, const float* __restrict__ scale,
    const float* __restrict__ bias, __nv_bfloat16* __restrict__ ht)
{
    __shared__ float tile[16 * 257];
    __shared__ float sh_s[8], sh_ss[8], s_stat[2];
    __shared__ float csc[16], cbi[16];

    int bi = blockIdx.x;           // b*32 + g
    int b = bi >> 5, g = bi & 31;
    const float* xg = x + (size_t)bi * 65536;

    float s = 0.f, ss = 0.f;
    const float4* xp = (const float4*)xg;
    for (int i = threadIdx.x; i < 16384; i += 256) {
        float4 t = xp[i];
        s  += t.x + t.y + t.z + t.w;
        ss += t.x * t.x + t.y * t.y + t.z * t.z + t.w * t.w;
    }
    int lane = threadIdx.x & 31, wrp = threadIdx.x >> 5;
#pragma unroll
    for (int o = 16; o; o >>= 1) {
        s  += __shfl_xor_sync(0xffffffffu, s, o);
        ss += __shfl_xor_sync(0xffffffffu, ss, o);
    }
    if (lane == 0) { sh_s[wrp] = s; sh_ss[wrp] = ss; }
    __syncthreads();
    if (threadIdx.x == 0) {
        float ts = 0.f, tss = 0.f;
        for (int i = 0; i < 8; i++) { ts += sh_s[i]; tss += sh_ss[i]; }
        float mean = ts / 65536.0f;
        float var  = tss / 65536.0f - mean * mean;
        s_stat[0] = mean;
        s_stat[1] = rsqrtf(var + 1e-6f);
    }
    __syncthreads();
    if (threadIdx.x < 16) {
        float sc = scale[g * 16 + threadIdx.x] * s_stat[1];
        csc[threadIdx.x] = sc;
        cbi[threadIdx.x] = bias[g * 16 + threadIdx.x] - s_stat[0] * sc;
    }
    __syncthreads();

    __nv_bfloat16* hb = ht + (size_t)b * 2097152 + g * 16;
    for (int l0 = 0; l0 < 4096; l0 += 256) {
#pragma unroll
        for (int c = 0; c < 16; c++)
            tile[c * 257 + threadIdx.x] =
                xg[c * 4096 + l0 + threadIdx.x] * csc[c] + cbi[c];
        __syncthreads();
#pragma unroll
        for (int rep = 0; rep < 16; rep++) {
            int idx = rep * 256 + threadIdx.x;
            int lp = idx >> 4, cc = idx & 15;
            hb[(size_t)(l0 + lp) * 512 + cc] =
                __float2bfloat16(tile[cc * 257 + lp]);
        }
        __syncthreads();
    }
}

// ---------------- row softmax over j (bf16 in/out, fp32 math) ------------------
__global__ void __launch_bounds__(256) softmax_kernel(__nv_bfloat16* __restrict__ S)
{
    __shared__ float shm[8], shsum[8];
    __shared__ float bmax, bsum;
    __nv_bfloat162* p = (__nv_bfloat162*)(S + (size_t)blockIdx.x * 4096);
    float2 v[8];
    float mx = -3.4e38f;
#pragma unroll
    for (int i = 0; i < 8; i++) {
        v[i] = __bfloat1622float2(p[threadIdx.x + (i << 8)]);
        mx = fmaxf(mx, fmaxf(v[i].x, v[i].y));
    }
    int lane = threadIdx.x & 31, wrp = threadIdx.x >> 5;
#pragma unroll
    for (int o = 16; o; o >>= 1) mx = fmaxf(mx, __shfl_xor_sync(0xffffffffu, mx, o));
    if (lane == 0) shm[wrp] = mx;
    __syncthreads();
    if (threadIdx.x == 0) {
        float m = shm[0];
        for (int i = 1; i < 8; i++) m = fmaxf(m, shm[i]);
        bmax = m;
    }
    __syncthreads();
    mx = bmax;
    float sum = 0.f;
#pragma unroll
    for (int i = 0; i < 8; i++) {
        v[i].x = __expf(v[i].x - mx);
        v[i].y = __expf(v[i].y - mx);
        sum += v[i].x + v[i].y;
    }
#pragma unroll
    for (int o = 16; o; o >>= 1) sum += __shfl_xor_sync(0xffffffffu, sum, o);
    if (lane == 0) shsum[wrp] = sum;
    __syncthreads();
    if (threadIdx.x == 0) {
        float s = 0.f;
        for (int i = 0; i < 8; i++) s += shsum[i];
        bsum = s;
    }
    __syncthreads();
    float inv = 1.0f / bsum;
#pragma unroll
    for (int i = 0; i < 8; i++)
        p[threadIdx.x + (i << 8)] =
            __float22bfloat162_rn(make_float2(v[i].x * inv, v[i].y * inv));
}

// -----------------------------------------------------------------------------
extern "C" void kernel_launch(void* const* d_in, const int* in_sizes, int n_in,
                              void* d_out, int out_size)
{
    (void)in_sizes; (void)n_in; (void)out_size;
    const float* x  = (const float*)d_in[0];
    const float* gs = (const float*)d_in[1];
    const float* gb = (const float*)d_in[2];
    const float* wq = (const float*)d_in[3];
    const float* bq = (const float*)d_in[4];
    const float* wk = (const float*)d_in[5];
    const float* bk = (const float*)d_in[6];
    const float* wv = (const float*)d_in[7];
    const float* bv = (const float*)d_in[8];
    const float* wp = (const float*)d_in[9];
    const float* bp = (const float*)d_in[10];
    float* out = (float*)d_out;

    __nv_bfloat16 *ht, *qt, *kt, *v, *s, *ot, *wqb, *wkb, *wvb, *wpb;
    cudaGetSymbolAddress((void**)&ht, g_ht);
    cudaGetSymbolAddress((void**)&qt, g_qt);
    cudaGetSymbolAddress((void**)&kt, g_kt);
    cudaGetSymbolAddress((void**)&v,  g_v);
    cudaGetSymbolAddress((void**)&s,  g_s);
    cudaGetSymbolAddress((void**)&ot, g_ot);
    cudaGetSymbolAddress((void**)&wqb, g_wq);
    cudaGetSymbolAddress((void**)&wkb, g_wk);
    cudaGetSymbolAddress((void**)&wvb, g_wv);
    cudaGetSymbolAddress((void**)&wpb, g_wp);

    cudaFuncSetAttribute(mm_bf16, cudaFuncAttributeMaxDynamicSharedMemorySize,
                         SMEM_TOTAL);

    const float SCALE = 0.044194173824159216f;  // 512^-0.5
    const int64_t LC = 2097152, LS = 16777216;

    cvt_w_kernel<<<dim3(256, 4), 256>>>(wq, wk, wv, wp, wqb, wkb, wvb, wpb);
    groupnorm_t_kernel<<<128, 256>>>(x, gs, gb, ht);

    // Q^T[l][c], K^T[l][c] : M=4096(l), N=512(c), K=512
    mm_bf16<<<dim3(4, 32, 4), 256, SMEM_TOTAL>>>(ht, 512, LC, wqb, 512, 0,
                                                 qt, 512, LC, 512, 1.0f,
                                                 nullptr, bq, nullptr, 0);
    mm_bf16<<<dim3(4, 32, 4), 256, SMEM_TOTAL>>>(ht, 512, LC, wkb, 512, 0,
                                                 kt, 512, LC, 512, 1.0f,
                                                 nullptr, bk, nullptr, 0);
    // V[c][l] : M=512(c), N=4096(l), K=512
    mm_bf16<<<dim3(32, 4, 4), 256, SMEM_TOTAL>>>(wvb, 512, 0, ht, 512, LC,
                                                 v, 4096, LC, 512, 1.0f,
                                                 bv, nullptr, nullptr, 0);
    // S[i][j] : M=N=4096, K=512
    mm_bf16<<<dim3(32, 32, 4), 256, SMEM_TOTAL>>>(qt, 512, LC, kt, 512, LC,
                                                  s, 4096, LS, 512, SCALE,
                                                  nullptr, nullptr, nullptr, 0);
    softmax_kernel<<<16384, 256>>>(s);
    // O^T[i][c] : M=4096(i), N=512(c), K=4096(j)
    mm_bf16<<<dim3(4, 32, 4), 256, SMEM_TOTAL>>>(s, 4096, LS, v, 4096, LC,
                                                 ot, 512, LC, 4096, 1.0f,
                                                 nullptr, nullptr, nullptr, 0);
    // out[c][l] = Wp * O + bp + x : M=512(c), N=4096(l), K=512
    mm_bf16<<<dim3(32, 4, 4), 256, SMEM_TOTAL>>>(wpb, 512, 0, ot, 512, LC,
                                                 out, 4096, LC, 512, 1.0f,
                                                 bp, nullptr, x, 1);
}

// round 5
// speedup vs baseline: 6.4126x; 1.0099x over previous
#include <cuda_runtime.h>
#include <cuda_bf16.h>
#include <cstdint>

// scratch (device globals) — b=4, c=512, l=4096, all intermediates bf16
__device__ __nv_bfloat16 g_ht[4ull * 4096 * 512];   // H^T [b][l][c]
__device__ __nv_bfloat16 g_qt[4ull * 4096 * 512];   // Q^T [b][l][c]
__device__ __nv_bfloat16 g_kt[4ull * 4096 * 512];   // K^T [b][l][c]
__device__ __nv_bfloat16 g_v [4ull * 512 * 4096];   // V   [b][c][l]
__device__ __nv_bfloat16 g_s [4ull * 4096 * 4096];  // P = exp(S*scale)
__device__ __nv_bfloat16 g_ot[4ull * 4096 * 512];   // O^T [b][l][c]
__device__ __nv_bfloat16 g_wq[512 * 512], g_wk[512 * 512];
__device__ __nv_bfloat16 g_wv[512 * 512], g_wp[512 * 512];
__device__ float g_l[4 * 4096];                      // softmax row sums

// ---------------- helpers ----------------------------------------------------
__device__ __forceinline__ uint32_t smem_u32(const void* p) {
    uint32_t a;
    asm("{ .reg .u64 t; cvta.to.shared.u64 t, %1; cvt.u32.u64 %0, t; }"
        : "=r"(a) : "l"(p));
    return a;
}

__device__ __forceinline__ void ldsm4(uint32_t& r0, uint32_t& r1, uint32_t& r2,
                                      uint32_t& r3, uint32_t addr) {
    asm volatile("ldmatrix.sync.aligned.m8n8.x4.shared.b16 {%0,%1,%2,%3}, [%4];"
                 : "=r"(r0), "=r"(r1), "=r"(r2), "=r"(r3) : "r"(addr));
}

__device__ __forceinline__ void mma_bf16(float (&c)[4], const uint32_t (&a)[4],
                                         const uint32_t (&b)[2]) {
    asm volatile(
        "mma.sync.aligned.m16n8k16.row.col.f32.bf16.bf16.f32 "
        "{%0,%1,%2,%3},{%4,%5,%6,%7},{%8,%9},{%0,%1,%2,%3};"
        : "+f"(c[0]), "+f"(c[1]), "+f"(c[2]), "+f"(c[3])
        : "r"(a[0]), "r"(a[1]), "r"(a[2]), "r"(a[3]), "r"(b[0]), "r"(b[1]));
}

// smem: 3 stages x (A 128x(32+8) = 10240B, B 256x(32+8) = 20480B) = 92160B
#define ROW_B 80
#define A_BYTES 10240
#define STG_BYTES 30720
#define SMEM_TOTAL 92160

// stage: A 128x32 bf16 + B 256x32 bf16, K-major, via cp.async 16B chunks
__device__ __forceinline__ void load_stage(
    uint32_t sbase, const __nv_bfloat16* __restrict__ Ab,
    const __nv_bfloat16* __restrict__ Bb, int64_t lda, int64_t ldb, int koff,
    int tid) {
#pragma unroll
    for (int rep = 0; rep < 6; rep++) {
        int u = tid + rep * 256;
        const __nv_bfloat16* g;
        uint32_t dst;
        if (u < 512) {
            int row = u >> 2, c16 = u & 3;
            g = Ab + (int64_t)row * lda + koff + c16 * 8;
            dst = sbase + row * ROW_B + c16 * 16;
        } else {
            int v = u - 512;
            int row = v >> 2, c16 = v & 3;
            g = Bb + (int64_t)row * ldb + koff + c16 * 8;
            dst = sbase + A_BYTES + row * ROW_B + c16 * 16;
        }
        asm volatile("cp.async.cg.shared.global [%0], [%1], 16;"
                     :: "r"(dst), "l"(g) : "memory");
    }
}

// ---------------- generic bf16 tensor-core GEMM -------------------------------
// CTA tile 128(m) x 256(n), 8 warps, warp tile 64x64.
// D[m][n] = f( alpha * sum_k A[z][m][k] * B[z][n][k] )
// mode 0: + bias_m/bias_n (+resid if out_f32)
// mode 1: p = exp(v); store bf16; atomicAdd row sums (of rounded p) to lsum
// mode 2: v *= 1/lsum[row]
__global__ void __launch_bounds__(256, 1) mm_bf16(
    const __nv_bfloat16* __restrict__ A, int64_t lda, int64_t astr,
    const __nv_bfloat16* __restrict__ B, int64_t ldb, int64_t bstr,
    void* __restrict__ C, int64_t ldc, int64_t cstr, int K, float alpha,
    const float* __restrict__ bias_m, const float* __restrict__ bias_n,
    const float* __restrict__ resid, float* __restrict__ lsum,
    int mode, int out_f32)
{
    extern __shared__ char smem[];
    uint32_t sb = smem_u32(smem);
    int tid = threadIdx.x, lane = tid & 31, wid = tid >> 5;
    int wm = wid & 1, wn = wid >> 1;
    int m0 = blockIdx.y * 128, n0 = blockIdx.x * 256, z = blockIdx.z;
    const __nv_bfloat16* Ab = A + (int64_t)z * astr + (int64_t)m0 * lda;
    const __nv_bfloat16* Bb = B + (int64_t)z * bstr + (int64_t)n0 * ldb;

    const int S = K >> 5;
    load_stage(sb, Ab, Bb, lda, ldb, 0, tid);
    asm volatile("cp.async.commit_group;" ::: "memory");
    if (S > 1) load_stage(sb + STG_BYTES, Ab, Bb, lda, ldb, 32, tid);
    asm volatile("cp.async.commit_group;" ::: "memory");

    float acc[4][8][4] = {};
    // precompute ldsm lane addressing
    uint32_t a_row = wm * 64 + (lane & 15);
    uint32_t a_cs = ((lane >> 4) << 3) * 2;
    uint32_t b_row = wn * 64 + (lane & 7) + ((lane >> 4) << 3);
    uint32_t b_cs = (((lane >> 3) & 1) << 3) * 2;

    for (int s = 0; s < S; s++) {
        asm volatile("cp.async.wait_group 1;" ::: "memory");
        __syncthreads();
        if (s + 2 < S)
            load_stage(sb + ((s + 2) % 3) * STG_BYTES, Ab, Bb, lda, ldb,
                       (s + 2) * 32, tid);
        asm volatile("cp.async.commit_group;" ::: "memory");

        uint32_t sa = sb + (s % 3) * STG_BYTES;
        uint32_t sB = sa + A_BYTES;
#pragma unroll
        for (int kk = 0; kk < 2; kk++) {
            uint32_t a[4][4], b[8][2];
#pragma unroll
            for (int i = 0; i < 4; i++)
                ldsm4(a[i][0], a[i][1], a[i][2], a[i][3],
                      sa + (a_row + i * 16) * ROW_B + kk * 32 + a_cs);
#pragma unroll
            for (int jt = 0; jt < 4; jt++) {
                uint32_t r0, r1, r2, r3;
                ldsm4(r0, r1, r2, r3,
                      sB + (b_row + jt * 16) * ROW_B + kk * 32 + b_cs);
                b[jt * 2][0] = r0; b[jt * 2][1] = r1;
                b[jt * 2 + 1][0] = r2; b[jt * 2 + 1][1] = r3;
            }
#pragma unroll
            for (int i = 0; i < 4; i++)
#pragma unroll
                for (int j = 0; j < 8; j++) mma_bf16(acc[i][j], a[i], b[j]);
        }
    }

    // ---------------- epilogue ----------------
#pragma unroll
    for (int i = 0; i < 4; i++) {
        int r0 = m0 + wm * 64 + i * 16 + (lane >> 2);
        float bm0 = bias_m ? bias_m[r0] : 0.0f;
        float bm1 = bias_m ? bias_m[r0 + 8] : 0.0f;
        float rl0 = 1.0f, rl1 = 1.0f;
        if (mode == 2) {
            rl0 = __fdividef(1.0f, lsum[z * 4096 + r0]);
            rl1 = __fdividef(1.0f, lsum[z * 4096 + r0 + 8]);
        }
        float rs0 = 0.0f, rs1 = 0.0f;
#pragma unroll
        for (int j = 0; j < 8; j++) {
            int cc = n0 + wn * 64 + j * 8 + (lane & 3) * 2;
            float v00 = acc[i][j][0] * alpha + bm0;
            float v01 = acc[i][j][1] * alpha + bm0;
            float v10 = acc[i][j][2] * alpha + bm1;
            float v11 = acc[i][j][3] * alpha + bm1;
            if (bias_n) {
                float b0 = bias_n[cc], b1 = bias_n[cc + 1];
                v00 += b0; v01 += b1; v10 += b0; v11 += b1;
            }
            if (mode == 1) {
                v00 = __expf(v00); v01 = __expf(v01);
                v10 = __expf(v10); v11 = __expf(v11);
            } else if (mode == 2) {
                v00 *= rl0; v01 *= rl0; v10 *= rl1; v11 *= rl1;
            }
            int64_t i0 = (int64_t)z * cstr + (int64_t)r0 * ldc + cc;
            int64_t i1 = i0 + 8 * ldc;
            if (out_f32) {
                float* Cf = (float*)C;
                if (resid) {
                    float2 t0 = *(const float2*)(resid + i0);
                    float2 t1 = *(const float2*)(resid + i1);
                    v00 += t0.x; v01 += t0.y; v10 += t1.x; v11 += t1.y;
                }
                *(float2*)(Cf + i0) = make_float2(v00, v01);
                *(float2*)(Cf + i1) = make_float2(v10, v11);
            } else {
                __nv_bfloat16* Cb = (__nv_bfloat16*)C;
                __nv_bfloat162 h0 = __float22bfloat162_rn(make_float2(v00, v01));
                __nv_bfloat162 h1 = __float22bfloat162_rn(make_float2(v10, v11));
                if (mode == 1) {
                    float2 q0 = __bfloat1622float2(h0);
                    float2 q1 = __bfloat1622float2(h1);
                    rs0 += q0.x + q0.y;
                    rs1 += q1.x + q1.y;
                }
                *(__nv_bfloat162*)(Cb + i0) = h0;
                *(__nv_bfloat162*)(Cb + i1) = h1;
            }
        }
        if (mode == 1) {
            rs0 += __shfl_xor_sync(0xffffffffu, rs0, 1);
            rs0 += __shfl_xor_sync(0xffffffffu, rs0, 2);
            rs1 += __shfl_xor_sync(0xffffffffu, rs1, 1);
            rs1 += __shfl_xor_sync(0xffffffffu, rs1, 2);
            if ((lane & 3) == 0) {
                atomicAdd(lsum + z * 4096 + r0, rs0);
                atomicAdd(lsum + z * 4096 + r0 + 8, rs1);
            }
        }
    }
}

// ---------------- zero the row-sum buffer -------------------------------------
__global__ void zero_l_kernel(float* __restrict__ l) {
    l[blockIdx.x * 1024 + threadIdx.x] = 0.0f;
}

// ---------------- weight fp32 -> bf16 -----------------------------------------
__global__ void __launch_bounds__(256) cvt_w_kernel(
    const float* __restrict__ w0, const float* __restrict__ w1,
    const float* __restrict__ w2, const float* __restrict__ w3,
    __nv_bfloat16* __restrict__ o0, __nv_bfloat16* __restrict__ o1,
    __nv_bfloat16* __restrict__ o2, __nv_bfloat16* __restrict__ o3)
{
    const float* w = blockIdx.y == 0 ? w0 : blockIdx.y == 1 ? w1
                     : blockIdx.y == 2 ? w2 : w3;
    __nv_bfloat16* o = blockIdx.y == 0 ? o0 : blockIdx.y == 1 ? o1
                       : blockIdx.y == 2 ? o2 : o3;
    int i = (blockIdx.x * 256 + threadIdx.x) * 4;
    float4 t = *(const float4*)(w + i);
    *(__nv_bfloat162*)(o + i) = __float22bfloat162_rn(make_float2(t.x, t.y));
    *(__nv_bfloat162*)(o + i + 2) = __float22bfloat162_rn(make_float2(t.z, t.w));
}

// ---------------- GroupNorm -> transposed bf16 H^T [b][l][c] -------------------
__global__ void __launch_bounds__(256) groupnorm_t_kernel(
    const float* __restrict__ x, const float* __restrict__ scale,
    const float* __restrict__ bias, __nv_bfloat16* __restrict__ ht)
{
    __shared__ float tile[16 * 257];
    __shared__ float sh_s[8], sh_ss[8], s_stat[2];
    __shared__ float csc[16], cbi[16];

    int bi = blockIdx.x;           // b*32 + g
    int b = bi >> 5, g = bi & 31;
    const float* xg = x + (size_t)bi * 65536;

    float s = 0.f, ss = 0.f;
    const float4* xp = (const float4*)xg;
    for (int i = threadIdx.x; i < 16384; i += 256) {
        float4 t = xp[i];
        s  += t.x + t.y + t.z + t.w;
        ss += t.x * t.x + t.y * t.y + t.z * t.z + t.w * t.w;
    }
    int lane = threadIdx.x & 31, wrp = threadIdx.x >> 5;
#pragma unroll
    for (int o = 16; o; o >>= 1) {
        s  += __shfl_xor_sync(0xffffffffu, s, o);
        ss += __shfl_xor_sync(0xffffffffu, ss, o);
    }
    if (lane == 0) { sh_s[wrp] = s; sh_ss[wrp] = ss; }
    __syncthreads();
    if (threadIdx.x == 0) {
        float ts = 0.f, tss = 0.f;
        for (int i = 0; i < 8; i++) { ts += sh_s[i]; tss += sh_ss[i]; }
        float mean = ts / 65536.0f;
        float var  = tss / 65536.0f - mean * mean;
        s_stat[0] = mean;
        s_stat[1] = rsqrtf(var + 1e-6f);
    }
    __syncthreads();
    if (threadIdx.x < 16) {
        float sc = scale[g * 16 + threadIdx.x] * s_stat[1];
        csc[threadIdx.x] = sc;
        cbi[threadIdx.x] = bias[g * 16 + threadIdx.x] - s_stat[0] * sc;
    }
    __syncthreads();

    __nv_bfloat16* hb = ht + (size_t)b * 2097152 + g * 16;
    for (int l0 = 0; l0 < 4096; l0 += 256) {
#pragma unroll
        for (int c = 0; c < 16; c++)
            tile[c * 257 + threadIdx.x] =
                xg[c * 4096 + l0 + threadIdx.x] * csc[c] + cbi[c];
        __syncthreads();
#pragma unroll
        for (int rep = 0; rep < 16; rep++) {
            int idx = rep * 256 + threadIdx.x;
            int lp = idx >> 4, cc = idx & 15;
            hb[(size_t)(l0 + lp) * 512 + cc] =
                __float2bfloat16(tile[cc * 257 + lp]);
        }
        __syncthreads();
    }
}

// -----------------------------------------------------------------------------
extern "C" void kernel_launch(void* const* d_in, const int* in_sizes, int n_in,
                              void* d_out, int out_size)
{
    (void)in_sizes; (void)n_in; (void)out_size;
    const float* x  = (const float*)d_in[0];
    const float* gs = (const float*)d_in[1];
    const float* gb = (const float*)d_in[2];
    const float* wq = (const float*)d_in[3];
    const float* bq = (const float*)d_in[4];
    const float* wk = (const float*)d_in[5];
    const float* bk = (const float*)d_in[6];
    const float* wv = (const float*)d_in[7];
    const float* bv = (const float*)d_in[8];
    const float* wp = (const float*)d_in[9];
    const float* bp = (const float*)d_in[10];
    float* out = (float*)d_out;

    __nv_bfloat16 *ht, *qt, *kt, *v, *s, *ot, *wqb, *wkb, *wvb, *wpb;
    float* l;
    cudaGetSymbolAddress((void**)&ht, g_ht);
    cudaGetSymbolAddress((void**)&qt, g_qt);
    cudaGetSymbolAddress((void**)&kt, g_kt);
    cudaGetSymbolAddress((void**)&v,  g_v);
    cudaGetSymbolAddress((void**)&s,  g_s);
    cudaGetSymbolAddress((void**)&ot, g_ot);
    cudaGetSymbolAddress((void**)&wqb, g_wq);
    cudaGetSymbolAddress((void**)&wkb, g_wk);
    cudaGetSymbolAddress((void**)&wvb, g_wv);
    cudaGetSymbolAddress((void**)&wpb, g_wp);
    cudaGetSymbolAddress((void**)&l,  g_l);

    cudaFuncSetAttribute(mm_bf16, cudaFuncAttributeMaxDynamicSharedMemorySize,
                         SMEM_TOTAL);

    const float SCALE = 0.044194173824159216f;  // 512^-0.5
    const int64_t LC = 2097152, LS = 16777216;

    cvt_w_kernel<<<dim3(256, 4), 256>>>(wq, wk, wv, wp, wqb, wkb, wvb, wpb);
    groupnorm_t_kernel<<<128, 256>>>(x, gs, gb, ht);
    zero_l_kernel<<<16, 1024>>>(l);

    // Q^T, K^T [l][c] : M=4096, N=512, K=512
    mm_bf16<<<dim3(2, 32, 4), 256, SMEM_TOTAL>>>(ht, 512, LC, wqb, 512, 0,
        qt, 512, LC, 512, 1.0f, nullptr, bq, nullptr, nullptr, 0, 0);
    mm_bf16<<<dim3(2, 32, 4), 256, SMEM_TOTAL>>>(ht, 512, LC, wkb, 512, 0,
        kt, 512, LC, 512, 1.0f, nullptr, bk, nullptr, nullptr, 0, 0);
    // V[c][l] : M=512, N=4096, K=512
    mm_bf16<<<dim3(16, 4, 4), 256, SMEM_TOTAL>>>(wvb, 512, 0, ht, 512, LC,
        v, 4096, LC, 512, 1.0f, bv, nullptr, nullptr, nullptr, 0, 0);
    // P[i][j] = exp(scale * Q.K) : M=N=4096, K=512 (+ row sums into l)
    mm_bf16<<<dim3(16, 32, 4), 256, SMEM_TOTAL>>>(qt, 512, LC, kt, 512, LC,
        s, 4096, LS, 512, SCALE, nullptr, nullptr, nullptr, l, 1, 0);
    // O^T[i][c] = (P @ V^T) / l[i] : M=4096, N=512, K=4096
    mm_bf16<<<dim3(2, 32, 4), 256, SMEM_TOTAL>>>(s, 4096, LS, v, 4096, LC,
        ot, 512, LC, 4096, 1.0f, nullptr, nullptr, nullptr, l, 2, 0);
    // out[c][l] = Wp @ O + bp + x : M=512, N=4096, K=512
    mm_bf16<<<dim3(16, 4, 4), 256, SMEM_TOTAL>>>(wpb, 512, 0, ot, 512, LC,
        out, 4096, LC, 512, 1.0f, bp, nullptr, x, nullptr, 0, 1);
}

// round 6
// speedup vs baseline: 7.7033x; 1.2013x over previous
#include <cuda_runtime.h>
#include <cuda_bf16.h>
#include <cstdint>

// scratch (device globals) — b=4, c=512, l=4096, all intermediates bf16
__device__ __nv_bfloat16 g_ht[4ull * 4096 * 512];   // H^T [b][l][c]
__device__ __nv_bfloat16 g_qt[4ull * 4096 * 512];   // Q^T [b][l][c]
__device__ __nv_bfloat16 g_kt[4ull * 4096 * 512];   // K^T [b][l][c]
__device__ __nv_bfloat16 g_v [4ull * 512 * 4096];   // V   [b][c][l]
__device__ __nv_bfloat16 g_s [4ull * 4096 * 4096];  // P = exp(S*scale)
__device__ __nv_bfloat16 g_ot[4ull * 4096 * 512];   // O^T [b][l][c]
__device__ __nv_bfloat16 g_wq[512 * 512], g_wk[512 * 512];
__device__ __nv_bfloat16 g_wv[512 * 512], g_wp[512 * 512];
__device__ float g_l[4 * 4096];                      // softmax row sums

// ---------------- helpers ----------------------------------------------------
__device__ __forceinline__ uint32_t smem_u32(const void* p) {
    uint32_t a;
    asm("{ .reg .u64 t; cvta.to.shared.u64 t, %1; cvt.u32.u64 %0, t; }"
        : "=r"(a) : "l"(p));
    return a;
}

__device__ __forceinline__ void ldsm4(uint32_t& r0, uint32_t& r1, uint32_t& r2,
                                      uint32_t& r3, uint32_t addr) {
    asm volatile("ldmatrix.sync.aligned.m8n8.x4.shared.b16 {%0,%1,%2,%3}, [%4];"
                 : "=r"(r0), "=r"(r1), "=r"(r2), "=r"(r3) : "r"(addr));
}

__device__ __forceinline__ void mma_bf16(float (&c)[4], const uint32_t (&a)[4],
                                         const uint32_t (&b)[2]) {
    asm volatile(
        "mma.sync.aligned.m16n8k16.row.col.f32.bf16.bf16.f32 "
        "{%0,%1,%2,%3},{%4,%5,%6,%7},{%8,%9},{%0,%1,%2,%3};"
        : "+f"(c[0]), "+f"(c[1]), "+f"(c[2]), "+f"(c[3])
        : "r"(a[0]), "r"(a[1]), "r"(a[2]), "r"(a[3]), "r"(b[0]), "r"(b[1]));
}

// smem: 3 stages x (A 128x(64+8) bf16 = 18432B, B same) = 110592B
#define ROW_B 144
#define A_BYTES 18432
#define STG_BYTES 36864
#define SMEM_TOTAL 110592

// stage: A 128x64 bf16 + B 128x64 bf16, K-major, cp.async 16B chunks
__device__ __forceinline__ void load_stage(
    uint32_t sbase, const __nv_bfloat16* __restrict__ Ab,
    const __nv_bfloat16* __restrict__ Bb, int64_t lda, int64_t ldb, int koff,
    int tid) {
#pragma unroll
    for (int rep = 0; rep < 8; rep++) {
        int u = tid + rep * 256;
        const __nv_bfloat16* g;
        uint32_t dst;
        if (u < 1024) {
            int row = u >> 3, c16 = u & 7;
            g = Ab + (int64_t)row * lda + koff + c16 * 8;
            dst = sbase + row * ROW_B + c16 * 16;
        } else {
            int vv = u - 1024;
            int row = vv >> 3, c16 = vv & 7;
            g = Bb + (int64_t)row * ldb + koff + c16 * 8;
            dst = sbase + A_BYTES + row * ROW_B + c16 * 16;
        }
        asm volatile("cp.async.cg.shared.global [%0], [%1], 16;"
                     :: "r"(dst), "l"(g) : "memory");
    }
}

// ---------------- generic bf16 tensor-core GEMM -------------------------------
// CTA tile 128(m) x 128(n), 8 warps, warp tile 64x32, BK=64 stages.
// D[m][n] = f( alpha * sum_k A[z][m][k] * B[z][n][k] )
// mode 0: + bias_m/bias_n (+resid if out_f32)
// mode 1: p = exp(v); store bf16; atomicAdd row sums (of rounded p) to lsum
// mode 2: v *= 1/lsum[row]
__global__ void __launch_bounds__(256, 2) mm_bf16(
    const __nv_bfloat16* __restrict__ A, int64_t lda, int64_t astr,
    const __nv_bfloat16* __restrict__ B, int64_t ldb, int64_t bstr,
    void* __restrict__ C, int64_t ldc, int64_t cstr, int K, float alpha,
    const float* __restrict__ bias_m, const float* __restrict__ bias_n,
    const float* __restrict__ resid, float* __restrict__ lsum,
    int mode, int out_f32)
{
    extern __shared__ char smem[];
    uint32_t sb = smem_u32(smem);
    int tid = threadIdx.x, lane = tid & 31, wid = tid >> 5;
    int wm = wid & 1, wn = wid >> 1;
    int m0 = blockIdx.y * 128, n0 = blockIdx.x * 128, z = blockIdx.z;
    const __nv_bfloat16* Ab = A + (int64_t)z * astr + (int64_t)m0 * lda;
    const __nv_bfloat16* Bb = B + (int64_t)z * bstr + (int64_t)n0 * ldb;

    const int S = K >> 6;      // BK = 64
    load_stage(sb, Ab, Bb, lda, ldb, 0, tid);
    asm volatile("cp.async.commit_group;" ::: "memory");
    if (S > 1) load_stage(sb + STG_BYTES, Ab, Bb, lda, ldb, 64, tid);
    asm volatile("cp.async.commit_group;" ::: "memory");

    float acc[4][4][4] = {};
    // ldsm lane addressing (byte offsets within a row)
    uint32_t a_row = wm * 64 + (lane & 15);
    uint32_t a_cs = ((lane >> 4) << 4);          // 0 or 16 bytes
    uint32_t b_row = wn * 32 + (lane & 7) + ((lane >> 4) << 3);
    uint32_t b_cs = (((lane >> 3) & 1) << 4);    // 0 or 16 bytes

    for (int s = 0; s < S; s++) {
        asm volatile("cp.async.wait_group 1;" ::: "memory");
        __syncthreads();
        if (s + 2 < S)
            load_stage(sb + ((s + 2) % 3) * STG_BYTES, Ab, Bb, lda, ldb,
                       (s + 2) * 64, tid);
        asm volatile("cp.async.commit_group;" ::: "memory");

        uint32_t sa = sb + (s % 3) * STG_BYTES;
        uint32_t sB = sa + A_BYTES;

        uint32_t afr[2][4][4];
        // prefetch A frags for kk=0
#pragma unroll
        for (int i = 0; i < 4; i++)
            ldsm4(afr[0][i][0], afr[0][i][1], afr[0][i][2], afr[0][i][3],
                  sa + (a_row + i * 16) * ROW_B + a_cs);
#pragma unroll
        for (int kk = 0; kk < 4; kk++) {
            int cur = kk & 1;
            if (kk < 3) {
                int nxt = cur ^ 1;
#pragma unroll
                for (int i = 0; i < 4; i++)
                    ldsm4(afr[nxt][i][0], afr[nxt][i][1], afr[nxt][i][2],
                          afr[nxt][i][3],
                          sa + (a_row + i * 16) * ROW_B + (kk + 1) * 32 + a_cs);
            }
            uint32_t b[4][2];
#pragma unroll
            for (int jt = 0; jt < 2; jt++) {
                uint32_t r0, r1, r2, r3;
                ldsm4(r0, r1, r2, r3,
                      sB + (b_row + jt * 16) * ROW_B + kk * 32 + b_cs);
                b[jt * 2][0] = r0; b[jt * 2][1] = r1;
                b[jt * 2 + 1][0] = r2; b[jt * 2 + 1][1] = r3;
            }
#pragma unroll
            for (int i = 0; i < 4; i++)
#pragma unroll
                for (int j = 0; j < 4; j++) mma_bf16(acc[i][j], afr[cur][i], b[j]);
        }
    }

    // ---------------- epilogue ----------------
#pragma unroll
    for (int i = 0; i < 4; i++) {
        int r0 = m0 + wm * 64 + i * 16 + (lane >> 2);
        float bm0 = bias_m ? bias_m[r0] : 0.0f;
        float bm1 = bias_m ? bias_m[r0 + 8] : 0.0f;
        float rl0 = 1.0f, rl1 = 1.0f;
        if (mode == 2) {
            rl0 = __fdividef(1.0f, lsum[z * 4096 + r0]);
            rl1 = __fdividef(1.0f, lsum[z * 4096 + r0 + 8]);
        }
        float rs0 = 0.0f, rs1 = 0.0f;
#pragma unroll
        for (int j = 0; j < 4; j++) {
            int cc = n0 + wn * 32 + j * 8 + (lane & 3) * 2;
            float v00 = acc[i][j][0] * alpha + bm0;
            float v01 = acc[i][j][1] * alpha + bm0;
            float v10 = acc[i][j][2] * alpha + bm1;
            float v11 = acc[i][j][3] * alpha + bm1;
            if (bias_n) {
                float b0 = bias_n[cc], b1 = bias_n[cc + 1];
                v00 += b0; v01 += b1; v10 += b0; v11 += b1;
            }
            if (mode == 1) {
                v00 = __expf(v00); v01 = __expf(v01);
                v10 = __expf(v10); v11 = __expf(v11);
            } else if (mode == 2) {
                v00 *= rl0; v01 *= rl0; v10 *= rl1; v11 *= rl1;
            }
            int64_t i0 = (int64_t)z * cstr + (int64_t)r0 * ldc + cc;
            int64_t i1 = i0 + 8 * ldc;
            if (out_f32) {
                float* Cf = (float*)C;
                if (resid) {
                    float2 t0 = *(const float2*)(resid + i0);
                    float2 t1 = *(const float2*)(resid + i1);
                    v00 += t0.x; v01 += t0.y; v10 += t1.x; v11 += t1.y;
                }
                *(float2*)(Cf + i0) = make_float2(v00, v01);
                *(float2*)(Cf + i1) = make_float2(v10, v11);
            } else {
                __nv_bfloat16* Cb = (__nv_bfloat16*)C;
                __nv_bfloat162 h0 = __float22bfloat162_rn(make_float2(v00, v01));
                __nv_bfloat162 h1 = __float22bfloat162_rn(make_float2(v10, v11));
                if (mode == 1) {
                    float2 q0 = __bfloat1622float2(h0);
                    float2 q1 = __bfloat1622float2(h1);
                    rs0 += q0.x + q0.y;
                    rs1 += q1.x + q1.y;
                }
                *(__nv_bfloat162*)(Cb + i0) = h0;
                *(__nv_bfloat162*)(Cb + i1) = h1;
            }
        }
        if (mode == 1) {
            rs0 += __shfl_xor_sync(0xffffffffu, rs0, 1);
            rs0 += __shfl_xor_sync(0xffffffffu, rs0, 2);
            rs1 += __shfl_xor_sync(0xffffffffu, rs1, 1);
            rs1 += __shfl_xor_sync(0xffffffffu, rs1, 2);
            if ((lane & 3) == 0) {
                atomicAdd(lsum + z * 4096 + r0, rs0);
                atomicAdd(lsum + z * 4096 + r0 + 8, rs1);
            }
        }
    }
}

// ---------------- zero the row-sum buffer -------------------------------------
__global__ void zero_l_kernel(float* __restrict__ l) {
    l[blockIdx.x * 1024 + threadIdx.x] = 0.0f;
}

// ---------------- weight fp32 -> bf16 -----------------------------------------
__global__ void __launch_bounds__(256) cvt_w_kernel(
    const float* __restrict__ w0, const float* __restrict__ w1,
    const float* __restrict__ w2, const float* __restrict__ w3,
    __nv_bfloat16* __restrict__ o0, __nv_bfloat16* __restrict__ o1,
    __nv_bfloat16* __restrict__ o2, __nv_bfloat16* __restrict__ o3)
{
    const float* w = blockIdx.y == 0 ? w0 : blockIdx.y == 1 ? w1
                     : blockIdx.y == 2 ? w2 : w3;
    __nv_bfloat16* o = blockIdx.y == 0 ? o0 : blockIdx.y == 1 ? o1
                       : blockIdx.y == 2 ? o2 : o3;
    int i = (blockIdx.x * 256 + threadIdx.x) * 4;
    float4 t = *(const float4*)(w + i);
    *(__nv_bfloat162*)(o + i) = __float22bfloat162_rn(make_float2(t.x, t.y));
    *(__nv_bfloat162*)(o + i + 2) = __float22bfloat162_rn(make_float2(t.z, t.w));
}

// ---------------- GroupNorm -> transposed bf16 H^T [b][l][c] -------------------
__global__ void __launch_bounds__(256) groupnorm_t_kernel(
    const float* __restrict__ x, const float* __restrict__ scale,
    const float* __restrict__ bias, __nv_bfloat16* __restrict__ ht)
{
    __shared__ float tile[16 * 257];
    __shared__ float sh_s[8], sh_ss[8], s_stat[2];
    __shared__ float csc[16], cbi[16];

    int bi = blockIdx.x;           // b*32 + g
    int b = bi >> 5, g = bi & 31;
    const float* xg = x + (size_t)bi * 65536;

    float s = 0.f, ss = 0.f;
    const float4* xp = (const float4*)xg;
    for (int i = threadIdx.x; i < 16384; i += 256) {
        float4 t = xp[i];
        s  += t.x + t.y + t.z + t.w;
        ss += t.x * t.x + t.y * t.y + t.z * t.z + t.w * t.w;
    }
    int lane = threadIdx.x & 31, wrp = threadIdx.x >> 5;
#pragma unroll
    for (int o = 16; o; o >>= 1) {
        s  += __shfl_xor_sync(0xffffffffu, s, o);
        ss += __shfl_xor_sync(0xffffffffu, ss, o);
    }
    if (lane == 0) { sh_s[wrp] = s; sh_ss[wrp] = ss; }
    __syncthreads();
    if (threadIdx.x == 0) {
        float ts = 0.f, tss = 0.f;
        for (int i = 0; i < 8; i++) { ts += sh_s[i]; tss += sh_ss[i]; }
        float mean = ts / 65536.0f;
        float var  = tss / 65536.0f - mean * mean;
        s_stat[0] = mean;
        s_stat[1] = rsqrtf(var + 1e-6f);
    }
    __syncthreads();
    if (threadIdx.x < 16) {
        float sc = scale[g * 16 + threadIdx.x] * s_stat[1];
        csc[threadIdx.x] = sc;
        cbi[threadIdx.x] = bias[g * 16 + threadIdx.x] - s_stat[0] * sc;
    }
    __syncthreads();

    __nv_bfloat16* hb = ht + (size_t)b * 2097152 + g * 16;
    for (int l0 = 0; l0 < 4096; l0 += 256) {
#pragma unroll
        for (int c = 0; c < 16; c++)
            tile[c * 257 + threadIdx.x] =
                xg[c * 4096 + l0 + threadIdx.x] * csc[c] + cbi[c];
        __syncthreads();
#pragma unroll
        for (int rep = 0; rep < 16; rep++) {
            int idx = rep * 256 + threadIdx.x;
            int lp = idx >> 4, cc = idx & 15;
            hb[(size_t)(l0 + lp) * 512 + cc] =
                __float2bfloat16(tile[cc * 257 + lp]);
        }
        __syncthreads();
    }
}

// -----------------------------------------------------------------------------
extern "C" void kernel_launch(void* const* d_in, const int* in_sizes, int n_in,
                              void* d_out, int out_size)
{
    (void)in_sizes; (void)n_in; (void)out_size;
    const float* x  = (const float*)d_in[0];
    const float* gs = (const float*)d_in[1];
    const float* gb = (const float*)d_in[2];
    const float* wq = (const float*)d_in[3];
    const float* bq = (const float*)d_in[4];
    const float* wk = (const float*)d_in[5];
    const float* bk = (const float*)d_in[6];
    const float* wv = (const float*)d_in[7];
    const float* bv = (const float*)d_in[8];
    const float* wp = (const float*)d_in[9];
    const float* bp = (const float*)d_in[10];
    float* out = (float*)d_out;

    __nv_bfloat16 *ht, *qt, *kt, *v, *s, *ot, *wqb, *wkb, *wvb, *wpb;
    float* l;
    cudaGetSymbolAddress((void**)&ht, g_ht);
    cudaGetSymbolAddress((void**)&qt, g_qt);
    cudaGetSymbolAddress((void**)&kt, g_kt);
    cudaGetSymbolAddress((void**)&v,  g_v);
    cudaGetSymbolAddress((void**)&s,  g_s);
    cudaGetSymbolAddress((void**)&ot, g_ot);
    cudaGetSymbolAddress((void**)&wqb, g_wq);
    cudaGetSymbolAddress((void**)&wkb, g_wk);
    cudaGetSymbolAddress((void**)&wvb, g_wv);
    cudaGetSymbolAddress((void**)&wpb, g_wp);
    cudaGetSymbolAddress((void**)&l,  g_l);

    cudaFuncSetAttribute(mm_bf16, cudaFuncAttributeMaxDynamicSharedMemorySize,
                         SMEM_TOTAL);

    const float SCALE = 0.044194173824159216f;  // 512^-0.5
    const int64_t LC = 2097152, LS = 16777216;

    cvt_w_kernel<<<dim3(256, 4), 256>>>(wq, wk, wv, wp, wqb, wkb, wvb, wpb);
    groupnorm_t_kernel<<<128, 256>>>(x, gs, gb, ht);
    zero_l_kernel<<<16, 1024>>>(l);

    // Q^T, K^T [l][c] : M=4096, N=512, K=512
    mm_bf16<<<dim3(4, 32, 4), 256, SMEM_TOTAL>>>(ht, 512, LC, wqb, 512, 0,
        qt, 512, LC, 512, 1.0f, nullptr, bq, nullptr, nullptr, 0, 0);
    mm_bf16<<<dim3(4, 32, 4), 256, SMEM_TOTAL>>>(ht, 512, LC, wkb, 512, 0,
        kt, 512, LC, 512, 1.0f, nullptr, bk, nullptr, nullptr, 0, 0);
    // V[c][l] : M=512, N=4096, K=512
    mm_bf16<<<dim3(32, 4, 4), 256, SMEM_TOTAL>>>(wvb, 512, 0, ht, 512, LC,
        v, 4096, LC, 512, 1.0f, bv, nullptr, nullptr, nullptr, 0, 0);
    // P[i][j] = exp(scale * Q.K) : M=N=4096, K=512 (+ row sums into l)
    mm_bf16<<<dim3(32, 32, 4), 256, SMEM_TOTAL>>>(qt, 512, LC, kt, 512, LC,
        s, 4096, LS, 512, SCALE, nullptr, nullptr, nullptr, l, 1, 0);
    // O^T[i][c] = (P @ V^T) / l[i] : M=4096, N=512, K=4096
    mm_bf16<<<dim3(4, 32, 4), 256, SMEM_TOTAL>>>(s, 4096, LS, v, 4096, LC,
        ot, 512, LC, 4096, 1.0f, nullptr, nullptr, nullptr, l, 2, 0);
    // out[c][l] = Wp @ O + bp + x : M=512, N=4096, K=512
    mm_bf16<<<dim3(32, 4, 4), 256, SMEM_TOTAL>>>(wpb, 512, 0, ot, 512, LC,
        out, 4096, LC, 512, 1.0f, bp, nullptr, x, nullptr, 0, 1);
}